// round 12
// baseline (speedup 1.0000x reference)
#include <cuda_runtime.h>
#include <cuda_fp16.h>
#include <cstdint>

#define NMAX   50000
#define EMAX   800000
#define EH     32
#define NET    3
#define CDIM   96      // NET*EH
#define ABDIM  192     // A(96) | B(96)
#define NBIN   150000  // NMAX*NET
#define NPART  586     // ceil(NBIN/256)

// ---- device scratch (static: no allocation allowed) ----
__device__ float  g_AB[NMAX * ABDIM];    // per-node A|B precompute (edge bias folded into A)
__device__ float  g_mean[NMAX * CDIM];   // mailbox means (written directly by gather)
__device__ float  g_H[NMAX * 64];        // layer-0 node output
__device__ __half g_Wstage[98304];       // all 4 weight sets staged as [kchunk][n][40] fp16
__device__ int    g_binc[NBIN];          // (dst,etype) histogram
__device__ int    g_part[1024];          // scan partials
__device__ int    g_off[NBIN + 1];       // CSR segment offsets
__device__ int    g_pos[NBIN];           // scatter cursors
__device__ int    g_sorted[EMAX];        // src indices sorted by (dst,etype)

// stage offsets (in halfs)
#define OFF_E0 0        // 4 kchunks * 192 * 40 = 30720
#define OFF_N0 30720    // 3 * 128 * 40        = 15360
#define OFF_E1 46080    // 2 * 192 * 40        = 15360
#define OFF_N1 61440    // 3 * 256 * 40        = 30720

// ===========================================================================
// Combined staging: four weight tensors -> fp16 [kchunk][n][40]; also zeroes
// the sort histogram. Launch with >= max(73728, NBIN) threads.
// ===========================================================================
__device__ __forceinline__ void stage_edge(const float* eW, int K, int off, int q) {
    int n = q / K, k = q - n * K;
    int half_ = n / CDIM, rem = n % CDIM, t = rem / EH, j = rem % EH;
    float v = eW[(size_t)t * (2 * K * EH) + (size_t)(half_ * K + k) * EH + j];
    g_Wstage[off + (((k >> 5) * ABDIM) + n) * 40 + (k & 31)] = __float2half_rn(v);
}
__device__ __forceinline__ void stage_node(const float* nW, int OUTD, int off, int q) {
    int NR = 2 * OUTD;
    int n = q / CDIM, k = q - n * CDIM;
    int t = n / OUTD, j = n - t * OUTD;
    float v = nW[(size_t)t * CDIM * OUTD + (size_t)k * OUTD + j];
    g_Wstage[off + (((k >> 5) * NR) + n) * 40 + (k & 31)] = __float2half_rn(v);
}
__global__ void prep_all(const float* __restrict__ eW0, const float* __restrict__ nW0,
                         const float* __restrict__ eW1, const float* __restrict__ nW1) {
    int idx = blockIdx.x * blockDim.x + threadIdx.x;
    if (idx < NBIN) g_binc[idx] = 0;
    if (idx < 24576)                  stage_edge(eW0, 128, OFF_E0, idx);
    else if (idx < 24576 + 12288)     stage_node(nW0,  64, OFF_N0, idx - 24576);
    else if (idx < 36864 + 12288)     stage_edge(eW1,  64, OFF_E1, idx - 36864);
    else if (idx < 49152 + 24576)     stage_node(nW1, 128, OFF_N1, idx - 49152);
}

// ===========================================================================
// Counting sort of edges by bin = dst*NET + etype (src index payload)
// ===========================================================================
__global__ void hist_kernel(const int* __restrict__ ei, const int* __restrict__ et, int E) {
    int e = blockIdx.x * blockDim.x + threadIdx.x;
    if (e >= E) return;
    atomicAdd(&g_binc[ei[E + e] * NET + et[e]], 1);
}
__global__ void scan1() {             // per-256 block sums
    __shared__ int s[256];
    int i = blockIdx.x * 256 + threadIdx.x;
    s[threadIdx.x] = (i < NBIN) ? g_binc[i] : 0;
    __syncthreads();
    for (int d = 128; d > 0; d >>= 1) {
        if (threadIdx.x < d) s[threadIdx.x] += s[threadIdx.x + d];
        __syncthreads();
    }
    if (threadIdx.x == 0) g_part[blockIdx.x] = s[0];
}
__global__ void scan2(int E) {        // exclusive scan of partials (1 block)
    __shared__ int s[1024];
    int t = threadIdx.x;
    int v = (t < NPART) ? g_part[t] : 0;
    s[t] = v; __syncthreads();
    for (int d = 1; d < 1024; d <<= 1) {
        int u = (t >= d) ? s[t - d] : 0;
        __syncthreads();
        s[t] += u;
        __syncthreads();
    }
    if (t < NPART) g_part[t] = s[t] - v;
    if (t == 0) g_off[NBIN] = E;
}
__global__ void scan3() {             // block-local exclusive scan + offsets
    __shared__ int s[256];
    int t = threadIdx.x;
    int i = blockIdx.x * 256 + t;
    int v = (i < NBIN) ? g_binc[i] : 0;
    s[t] = v; __syncthreads();
    for (int d = 1; d < 256; d <<= 1) {
        int u = (t >= d) ? s[t - d] : 0;
        __syncthreads();
        s[t] += u;
        __syncthreads();
    }
    if (i < NBIN) {
        int off = g_part[blockIdx.x] + s[t] - v;
        g_off[i] = off;
        g_pos[i] = off;
    }
}
__global__ void scatter_kernel(const int* __restrict__ ei, const int* __restrict__ et, int E) {
    int e = blockIdx.x * blockDim.x + threadIdx.x;
    if (e >= E) return;
    int bin = ei[E + e] * NET + et[e];
    int pos = atomicAdd(&g_pos[bin], 1);
    g_sorted[pos] = ei[e];
}

// ===========================================================================
// Gather-side edge reduction + mean. One warp per dst; 4 subgroups x 8 lanes.
// mean[dst, t*32+..] = sum over type-t in-edges of relu(A[src,t]+B[dst,t]) / max(cnt,1)
// (edge bias already folded into A). Writes g_mean directly; no atomics.
// ===========================================================================
__global__ __launch_bounds__(256) void gather_kernel(int nDst) {
    int warp = (blockIdx.x * 256 + threadIdx.x) >> 5;
    if (warp >= nDst) return;
    const int lane = threadIdx.x & 31;
    const int sub = lane >> 3, l = lane & 7;
    const int dst = warp;

    float4 bt[NET];
#pragma unroll
    for (int t = 0; t < NET; t++)
        bt[t] = *(const float4*)(g_AB + (size_t)dst * ABDIM + CDIM + t * EH + l * 4);

    int o = (lane < 4) ? g_off[dst * NET + lane] : 0;
    int ob[4];
#pragma unroll
    for (int q = 0; q < 4; q++) ob[q] = __shfl_sync(0xffffffffu, o, q);

#pragma unroll
    for (int t = 0; t < NET; t++) {
        const int s = ob[t], epos = ob[t + 1];
        float4 acc = make_float4(0.f, 0.f, 0.f, 0.f);
        int i = s + sub;
        for (; i + 4 < epos; i += 8) {
            int s1 = g_sorted[i], s2 = g_sorted[i + 4];
            float4 a1 = *(const float4*)(g_AB + (size_t)s1 * ABDIM + t * EH + l * 4);
            float4 a2 = *(const float4*)(g_AB + (size_t)s2 * ABDIM + t * EH + l * 4);
            acc.x += fmaxf(a1.x + bt[t].x, 0.f) + fmaxf(a2.x + bt[t].x, 0.f);
            acc.y += fmaxf(a1.y + bt[t].y, 0.f) + fmaxf(a2.y + bt[t].y, 0.f);
            acc.z += fmaxf(a1.z + bt[t].z, 0.f) + fmaxf(a2.z + bt[t].z, 0.f);
            acc.w += fmaxf(a1.w + bt[t].w, 0.f) + fmaxf(a2.w + bt[t].w, 0.f);
        }
        if (i < epos) {
            int s1 = g_sorted[i];
            float4 a1 = *(const float4*)(g_AB + (size_t)s1 * ABDIM + t * EH + l * 4);
            acc.x += fmaxf(a1.x + bt[t].x, 0.f);
            acc.y += fmaxf(a1.y + bt[t].y, 0.f);
            acc.z += fmaxf(a1.z + bt[t].z, 0.f);
            acc.w += fmaxf(a1.w + bt[t].w, 0.f);
        }
#pragma unroll
        for (int d = 8; d <= 16; d <<= 1) {
            acc.x += __shfl_xor_sync(0xffffffffu, acc.x, d);
            acc.y += __shfl_xor_sync(0xffffffffu, acc.y, d);
            acc.z += __shfl_xor_sync(0xffffffffu, acc.z, d);
            acc.w += __shfl_xor_sync(0xffffffffu, acc.w, d);
        }
        if (sub == 0) {
            float inv = 1.f / (float)max(epos - s, 1);
            float4 r = make_float4(acc.x * inv, acc.y * inv, acc.z * inv, acc.w * inv);
            *(float4*)(g_mean + (size_t)dst * CDIM + t * EH + l * 4) = r;
        }
    }
}

// ===========================================================================
// fp16 mma.sync GEMM, A-fragments direct from global (each element read once
// per slab), full W slab in smem (one barrier). 128 rows/block, 256 threads,
// CHUNK-wide column slab per blockIdx.y.
//   FUSED=false (AB gemm): slab 0 adds edge bias (A half, cols<96).
//   FUSED=true (node gemm): slab == node type; select + bias + relu.
// ===========================================================================
__device__ __forceinline__ uint32_t pack2(float a, float b) {
    __half2 h = __floats2half2_rn(a, b);
    return *reinterpret_cast<uint32_t*>(&h);
}
template <int K, int NTOT, int CHUNK, int WOFF, bool FUSED>
__global__ __launch_bounds__(256) void mma_gemm(const float* __restrict__ X,
                                                const int* __restrict__ nt,
                                                const float* __restrict__ bias,
                                                float* __restrict__ out, int n) {
    constexpr int NB = CHUNK / 8;
    constexpr int NKC = K / 32;
    __shared__ __align__(16) __half Ws[NKC][CHUNK][40];

    const int tid = threadIdx.x;
    const int lane = tid & 31, wid = tid >> 5;
    const int gid = lane >> 2, tig = lane & 3;
    const int base = blockIdx.x * 128;
    const int cb = blockIdx.y * CHUNK;
    const int wr = wid * 16;

    // full W slab: linear int4 copy per kchunk
    {
        const __half* wsrc = g_Wstage + WOFF;
        int4* wdst = (int4*)&Ws[0][0][0];
        for (int idx = tid; idx < NKC * CHUNK * 5; idx += 256) {
            int kc = idx / (CHUNK * 5), r = idx - kc * (CHUNK * 5);
            wdst[idx] = ((const int4*)(wsrc + (size_t)(kc * NTOT + cb) * 40))[r];
        }
    }
    __syncthreads();

    const int r0 = base + wr + gid, r1 = r0 + 8;
    const float* x0 = X + (size_t)min(r0, n - 1) * K;
    const float* x1 = X + (size_t)min(r1, n - 1) * K;

    float c[NB][4];
#pragma unroll
    for (int nb = 0; nb < NB; nb++)
#pragma unroll
        for (int q = 0; q < 4; q++) c[nb][q] = 0.f;

#pragma unroll
    for (int kc = 0; kc < NKC; kc++) {
#pragma unroll
        for (int ks = 0; ks < 2; ks++) {
            const int kg = kc * 32 + ks * 16 + 2 * tig;   // global k of fragment
            float2 f0 = *(const float2*)(x0 + kg);
            float2 f1 = *(const float2*)(x1 + kg);
            float2 f2 = *(const float2*)(x0 + kg + 8);
            float2 f3 = *(const float2*)(x1 + kg + 8);
            uint32_t a0 = pack2(f0.x, f0.y);
            uint32_t a1 = pack2(f1.x, f1.y);
            uint32_t a2 = pack2(f2.x, f2.y);
            uint32_t a3 = pack2(f3.x, f3.y);
            const int kk = ks * 16 + 2 * tig;
#pragma unroll
            for (int nb = 0; nb < NB; nb++) {
                uint32_t b0 = *(const uint32_t*)&Ws[kc][nb * 8 + gid][kk];
                uint32_t b1 = *(const uint32_t*)&Ws[kc][nb * 8 + gid][kk + 8];
                asm volatile(
                    "mma.sync.aligned.m16n8k16.row.col.f32.f16.f16.f32 "
                    "{%0,%1,%2,%3}, {%4,%5,%6,%7}, {%8,%9}, {%0,%1,%2,%3};"
                    : "+f"(c[nb][0]), "+f"(c[nb][1]), "+f"(c[nb][2]), "+f"(c[nb][3])
                    : "r"(a0), "r"(a1), "r"(a2), "r"(a3), "r"(b0), "r"(b1));
            }
        }
    }

    // ---- epilogue (fp32) ----
    if (!FUSED) {
#pragma unroll
        for (int h = 0; h < 2; h++) {
            int row = base + wr + gid + 8 * h;
            if (row < n) {
#pragma unroll
                for (int nb = 0; nb < NB; nb++) {
                    int col = cb + nb * 8 + 2 * tig;
                    float2 v = make_float2(c[nb][2 * h], c[nb][2 * h + 1]);
                    if (blockIdx.y == 0) {          // A half: fold edge bias
                        float2 b = *(const float2*)(bias + col);
                        v.x += b.x; v.y += b.y;
                    }
                    *(float2*)(out + (size_t)row * NTOT + col) = v;
                }
            }
        }
    } else {
        const int t = blockIdx.y;                   // slab == node type
#pragma unroll
        for (int h = 0; h < 2; h++) {
            int row = base + wr + gid + 8 * h;
            if (row < n && nt[row] == t) {
#pragma unroll
                for (int nb = 0; nb < NB; nb++) {
                    int col = nb * 8 + 2 * tig;
                    float2 b = *(const float2*)(bias + t * CHUNK + col);
                    float2 v;
                    v.x = fmaxf(c[nb][2 * h] + b.x, 0.f);
                    v.y = fmaxf(c[nb][2 * h + 1] + b.y, 0.f);
                    *(float2*)(out + (size_t)row * CHUNK + col) = v;
                }
            }
        }
    }
}

// ===========================================================================
extern "C" void kernel_launch(void* const* d_in, const int* in_sizes, int n_in,
                              void* d_out, int out_size) {
    const float* nf  = (const float*)d_in[0];
    const int*   ei  = (const int*)  d_in[1];
    const int*   et  = (const int*)  d_in[2];
    const int*   nt  = (const int*)  d_in[3];
    const float* eW0 = (const float*)d_in[4];
    const float* eb0 = (const float*)d_in[5];
    const float* nW0 = (const float*)d_in[6];
    const float* nb0 = (const float*)d_in[7];
    const float* eW1 = (const float*)d_in[8];
    const float* eb1 = (const float*)d_in[9];
    const float* nW1 = (const float*)d_in[10];
    const float* nb1 = (const float*)d_in[11];
    float* out = (float*)d_out;

    const int N = in_sizes[3];
    const int E = in_sizes[2];

    float *pAB, *pMean, *pH;
    cudaGetSymbolAddress((void**)&pAB,   g_AB);
    cudaGetSymbolAddress((void**)&pMean, g_mean);
    cudaGetSymbolAddress((void**)&pH,    g_H);

    const int nb128 = (N + 127) / 128;
    const dim3 g2(nb128, 2);
    const int gE = (E + 255) / 256;
    const int gD = (N + 7) / 8;       // gather: 1 warp/dst, 8 warps/block

    // ---- weight staging + edge sort (once) ----
    prep_all<<<(NBIN + 255) / 256, 256>>>(eW0, nW0, eW1, nW1);
    hist_kernel<<<gE, 256>>>(ei, et, E);
    scan1<<<NPART, 256>>>();
    scan2<<<1, 1024>>>(E);
    scan3<<<NPART, 256>>>();
    scatter_kernel<<<gE, 256>>>(ei, et, E);

    // ---------------- layer 0 (128 -> 64) ----------------
    mma_gemm<128, 192, 96, OFF_E0, false><<<g2, 256>>>(nf, nullptr, eb0, pAB, N);
    gather_kernel<<<gD, 256>>>(N);
    mma_gemm<96, 128, 64, OFF_N0, true><<<g2, 256>>>(pMean, nt, nb0, pH, N);

    // ---------------- layer 1 (64 -> 128) ----------------
    mma_gemm<64, 192, 96, OFF_E1, false><<<g2, 256>>>(pH, nullptr, eb1, pAB, N);
    gather_kernel<<<gD, 256>>>(N);
    mma_gemm<96, 256, 128, OFF_N1, true><<<g2, 256>>>(pMean, nt, nb1, out, N);
}

// round 13
// speedup vs baseline: 1.1762x; 1.1762x over previous
#include <cuda_runtime.h>
#include <cuda_fp16.h>
#include <cstdint>

#define NMAX   50000
#define EH     32
#define NET    3
#define CDIM   96      // NET*EH
#define ABDIM  192     // A(96) | B(96)

// ---- device scratch (static: no allocation allowed) ----
__device__ __half g_ABh[NMAX * ABDIM];   // per-node A|B precompute, fp16 (edge bias folded into A)
__device__ float  g_accum[NMAX * CDIM];  // scatter accumulators (fp32)
__device__ float  g_cnt[NMAX * NET];     // per (node, etype) counts
__device__ float  g_H[NMAX * 64];        // layer-0 node output
__device__ __half g_Wstage[98304];       // all 4 weight sets staged as [kchunk][n][40] fp16

// stage offsets (in halfs)
#define OFF_E0 0        // 4 kchunks * 192 * 40 = 30720
#define OFF_N0 30720    // 3 * 128 * 40        = 15360
#define OFF_E1 46080    // 2 * 192 * 40        = 15360
#define OFF_N1 61440    // 3 * 256 * 40        = 30720

// ===========================================================================
// Combined weight staging: all four weight tensors -> fp16 [kchunk][n][40]
// ===========================================================================
__device__ __forceinline__ void stage_edge(const float* eW, int K, int off, int q) {
    int n = q / K, k = q - n * K;
    int half_ = n / CDIM, rem = n % CDIM, t = rem / EH, j = rem % EH;
    float v = eW[(size_t)t * (2 * K * EH) + (size_t)(half_ * K + k) * EH + j];
    g_Wstage[off + (((k >> 5) * ABDIM) + n) * 40 + (k & 31)] = __float2half_rn(v);
}
__device__ __forceinline__ void stage_node(const float* nW, int OUTD, int off, int q) {
    int NR = 2 * OUTD;
    int n = q / CDIM, k = q - n * CDIM;
    int t = n / OUTD, j = n - t * OUTD;
    float v = nW[(size_t)t * CDIM * OUTD + (size_t)k * OUTD + j];
    g_Wstage[off + (((k >> 5) * NR) + n) * 40 + (k & 31)] = __float2half_rn(v);
}
__global__ void prep_all(const float* __restrict__ eW0, const float* __restrict__ nW0,
                         const float* __restrict__ eW1, const float* __restrict__ nW1) {
    int idx = blockIdx.x * blockDim.x + threadIdx.x;
    if (idx < 24576)                  stage_edge(eW0, 128, OFF_E0, idx);
    else if (idx < 24576 + 12288)     stage_node(nW0,  64, OFF_N0, idx - 24576);
    else if (idx < 36864 + 12288)     stage_edge(eW1,  64, OFF_E1, idx - 36864);
    else if (idx < 49152 + 24576)     stage_node(nW1, 128, OFF_N1, idx - 49152);
}

// ===========================================================================
// fp16 mma.sync GEMM: 128 rows/block, 256 threads, CHUNK-wide column slab per
// blockIdx.y. A-fragments loaded DIRECTLY from global (one read per element
// per slab, no Xs smem, no per-chunk syncs); full W slab in smem (1 barrier).
//   FUSED=false (AB gemm): epilogue writes fp16 to g_ABh; slab 0 adds edge
//       bias (A half) and zeroes g_accum rows (+ g_cnt when ZCNT).
//   FUSED=true (node gemm): X = g_accum / max(cnt,1) on load; slab == node
//       type; epilogue does select + bias + relu into out[row][CHUNK] (fp32).
// ===========================================================================
__device__ __forceinline__ uint32_t pack2(float a, float b) {
    __half2 h = __floats2half2_rn(a, b);
    return *reinterpret_cast<uint32_t*>(&h);
}
template <int K, int NTOT, int CHUNK, int WOFF, bool FUSED, bool ZCNT>
__global__ __launch_bounds__(256) void mma_gemm(const float* __restrict__ X,
                                                const float* __restrict__ cnt,
                                                const int* __restrict__ nt,
                                                const float* __restrict__ bias,
                                                float* __restrict__ out, int n) {
    constexpr int NB = CHUNK / 8;
    constexpr int NKC = K / 32;
    __shared__ __align__(16) __half Ws[NKC][CHUNK][40];

    const int tid = threadIdx.x;
    const int lane = tid & 31, wid = tid >> 5;
    const int gid = lane >> 2, tig = lane & 3;
    const int base = blockIdx.x * 128;
    const int cb = blockIdx.y * CHUNK;
    const int wr = wid * 16;

    // full W slab: linear int4 copy per kchunk (only barrier in the kernel)
    {
        const __half* wsrc = g_Wstage + WOFF;
        int4* wdst = (int4*)&Ws[0][0][0];
        for (int idx = tid; idx < NKC * CHUNK * 5; idx += 256) {
            int kc = idx / (CHUNK * 5), r = idx - kc * (CHUNK * 5);
            wdst[idx] = ((const int4*)(wsrc + (size_t)(kc * NTOT + cb) * 40))[r];
        }
    }
    __syncthreads();

    const int r0 = base + wr + gid, r1 = r0 + 8;
    const int rc0 = min(r0, n - 1), rc1 = min(r1, n - 1);
    const float* x0 = X + (size_t)rc0 * K;
    const float* x1 = X + (size_t)rc1 * K;

    float c[NB][4];
#pragma unroll
    for (int nb = 0; nb < NB; nb++)
#pragma unroll
        for (int q = 0; q < 4; q++) c[nb][q] = 0.f;

#pragma unroll
    for (int kc = 0; kc < NKC; kc++) {
        float s0 = 1.f, s1 = 1.f;
        if (FUSED) {
            s0 = 1.0f / fmaxf(cnt[rc0 * NET + kc], 1.0f);
            s1 = 1.0f / fmaxf(cnt[rc1 * NET + kc], 1.0f);
        }
#pragma unroll
        for (int ks = 0; ks < 2; ks++) {
            const int kg = kc * 32 + ks * 16 + 2 * tig;   // global k of fragment
            float2 f0 = *(const float2*)(x0 + kg);
            float2 f1 = *(const float2*)(x1 + kg);
            float2 f2 = *(const float2*)(x0 + kg + 8);
            float2 f3 = *(const float2*)(x1 + kg + 8);
            uint32_t a0 = pack2(f0.x * s0, f0.y * s0);
            uint32_t a1 = pack2(f1.x * s1, f1.y * s1);
            uint32_t a2 = pack2(f2.x * s0, f2.y * s0);
            uint32_t a3 = pack2(f3.x * s1, f3.y * s1);
            const int kk = ks * 16 + 2 * tig;
#pragma unroll
            for (int nb = 0; nb < NB; nb++) {
                uint32_t b0 = *(const uint32_t*)&Ws[kc][nb * 8 + gid][kk];
                uint32_t b1 = *(const uint32_t*)&Ws[kc][nb * 8 + gid][kk + 8];
                asm volatile(
                    "mma.sync.aligned.m16n8k16.row.col.f32.f16.f16.f32 "
                    "{%0,%1,%2,%3}, {%4,%5,%6,%7}, {%8,%9}, {%0,%1,%2,%3};"
                    : "+f"(c[nb][0]), "+f"(c[nb][1]), "+f"(c[nb][2]), "+f"(c[nb][3])
                    : "r"(a0), "r"(a1), "r"(a2), "r"(a3), "r"(b0), "r"(b1));
            }
        }
    }

    // ---- epilogue ----
    if (!FUSED) {
        // write fp16 AB table (bias folded into A half by slab 0)
#pragma unroll
        for (int h = 0; h < 2; h++) {
            int row = base + wr + gid + 8 * h;
            if (row < n) {
#pragma unroll
                for (int nb = 0; nb < NB; nb++) {
                    int col = cb + nb * 8 + 2 * tig;
                    float vx = c[nb][2 * h], vy = c[nb][2 * h + 1];
                    if (blockIdx.y == 0) {          // A half: fold edge bias
                        float2 b = *(const float2*)(bias + col);
                        vx += b.x; vy += b.y;
                    }
                    *(__half2*)(g_ABh + (size_t)row * ABDIM + col) = __floats2half2_rn(vx, vy);
                }
            }
        }
        // fused zeroing of scatter state for the edge pass (slab 0 does it)
        if (blockIdx.y == 0) {
            float4 z = make_float4(0.f, 0.f, 0.f, 0.f);
            for (int idx = lane; idx < 16 * 24; idx += 32) {
                int r = idx / 24, q = idx - r * 24;
                int row = base + wr + r;
                if (row < n) ((float4*)(g_accum + (size_t)row * CDIM))[q] = z;
            }
            if (ZCNT && lane < 16) {
                int row = base + wr + lane;
                if (row < n) {
                    g_cnt[row * NET] = 0.f;
                    g_cnt[row * NET + 1] = 0.f;
                    g_cnt[row * NET + 2] = 0.f;
                }
            }
        }
    } else {
        const int t = blockIdx.y;                   // slab == node type
#pragma unroll
        for (int h = 0; h < 2; h++) {
            int row = base + wr + gid + 8 * h;
            if (row < n && nt[row] == t) {
#pragma unroll
                for (int nb = 0; nb < NB; nb++) {
                    int col = nb * 8 + 2 * tig;
                    float2 b = *(const float2*)(bias + t * CHUNK + col);
                    float2 v;
                    v.x = fmaxf(c[nb][2 * h] + b.x, 0.f);
                    v.y = fmaxf(c[nb][2 * h + 1] + b.y, 0.f);
                    *(float2*)(out + (size_t)row * CHUNK + col) = v;
                }
            }
        }
    }
}

// ===========================================================================
// Edge pass: 8 threads / edge. A/B gathered as fp16 (half bytes of R11),
// compute fp32, red.v4.f32 scatter into accum[dst]. Bias already in A.
// ===========================================================================
template <bool COUNT>
__global__ __launch_bounds__(256) void edge_kernel(const int* __restrict__ ei,
                                                   const int* __restrict__ et, int E) {
    int gid = blockIdx.x * blockDim.x + threadIdx.x;
    int e = gid >> 3;
    if (e >= E) return;
    int l = gid & 7;
    int src = ei[e], dst = ei[E + e], t = et[e];

    uint2 ar = *(const uint2*)(g_ABh + (size_t)src * ABDIM + t * EH + l * 4);
    uint2 br = *(const uint2*)(g_ABh + (size_t)dst * ABDIM + CDIM + t * EH + l * 4);
    float2 a0 = __half22float2(*(__half2*)&ar.x);
    float2 a1 = __half22float2(*(__half2*)&ar.y);
    float2 b0 = __half22float2(*(__half2*)&br.x);
    float2 b1 = __half22float2(*(__half2*)&br.y);
    float mx = fmaxf(a0.x + b0.x, 0.f);
    float my = fmaxf(a0.y + b0.y, 0.f);
    float mz = fmaxf(a1.x + b1.x, 0.f);
    float mw = fmaxf(a1.y + b1.y, 0.f);

    float* p = g_accum + (size_t)dst * CDIM + t * EH + l * 4;
    asm volatile("red.global.add.v4.f32 [%0], {%1,%2,%3,%4};"
                 :: "l"(p), "f"(mx), "f"(my), "f"(mz), "f"(mw) : "memory");
    if (COUNT && l == 0) atomicAdd(g_cnt + (size_t)dst * NET + t, 1.0f);
}

// ===========================================================================
extern "C" void kernel_launch(void* const* d_in, const int* in_sizes, int n_in,
                              void* d_out, int out_size) {
    const float* nf  = (const float*)d_in[0];
    const int*   ei  = (const int*)  d_in[1];
    const int*   et  = (const int*)  d_in[2];
    const int*   nt  = (const int*)  d_in[3];
    const float* eW0 = (const float*)d_in[4];
    const float* eb0 = (const float*)d_in[5];
    const float* nW0 = (const float*)d_in[6];
    const float* nb0 = (const float*)d_in[7];
    const float* eW1 = (const float*)d_in[8];
    const float* eb1 = (const float*)d_in[9];
    const float* nW1 = (const float*)d_in[10];
    const float* nb1 = (const float*)d_in[11];
    float* out = (float*)d_out;

    const int N = in_sizes[3];
    const int E = in_sizes[2];

    float *pAcc, *pCnt, *pH;
    cudaGetSymbolAddress((void**)&pAcc, g_accum);
    cudaGetSymbolAddress((void**)&pCnt, g_cnt);
    cudaGetSymbolAddress((void**)&pH,   g_H);

    const int nb128 = (N + 127) / 128;
    const dim3 g2(nb128, 2);
    const int gEdge = (E * 8 + 255) / 256;

    // one staging kernel for all four weight tensors
    prep_all<<<(73728 + 255) / 256, 256>>>(eW0, nW0, eW1, nW1);

    // ---------------- layer 0 (128 -> 64) ----------------
    mma_gemm<128, 192, 96, OFF_E0, false, true><<<g2, 256>>>(nf, nullptr, nullptr, eb0, nullptr, N);
    edge_kernel<true><<<gEdge, 256>>>(ei, et, E);
    mma_gemm<96, 128, 64, OFF_N0, true, false><<<g2, 256>>>(pAcc, pCnt, nt, nb0, pH, N);

    // ---------------- layer 1 (64 -> 128) ----------------
    mma_gemm<64, 192, 96, OFF_E1, false, false><<<g2, 256>>>(pH, nullptr, nullptr, eb1, nullptr, N);
    edge_kernel<false><<<gEdge, 256>>>(ei, et, E);
    mma_gemm<96, 256, 128, OFF_N1, true, false><<<g2, 256>>>(pAcc, pCnt, nt, nb1, out, N);
}

// round 14
// speedup vs baseline: 1.2259x; 1.0422x over previous
#include <cuda_runtime.h>
#include <cuda_fp16.h>
#include <cstdint>

#define NMAX   50000
#define EH     32
#define NET    3
#define CDIM   96      // NET*EH
#define ABDIM  192     // A(96) | B(96)

// ---- device scratch (static: no allocation allowed) ----
__device__ __half g_ABh[NMAX * ABDIM];   // per-node A|B precompute, fp16 (edge bias folded into A)
__device__ float  g_accum[NMAX * CDIM];  // scatter accumulators (fp32)
__device__ float  g_cnt[NMAX * NET];     // per (node, etype) counts
__device__ __half g_Hh[NMAX * 64];       // layer-0 node output (fp16)
__device__ __half g_Wstage[98304];       // all 4 weight sets staged as [kchunk][n][40] fp16
__device__ int    g_perm[NMAX];          // nodes partitioned by type
__device__ int    g_n0, g_c0, g_c1;      // partition counters

// stage offsets (in halfs)
#define OFF_E0 0        // 4 kchunks * 192 * 40 = 30720
#define OFF_N0 30720    // 3 * 128 * 40        = 15360
#define OFF_E1 46080    // 2 * 192 * 40        = 15360
#define OFF_N1 61440    // 3 * 256 * 40        = 30720

// ===========================================================================
// Combined weight staging (+ zero partition counters)
// ===========================================================================
__device__ __forceinline__ void stage_edge(const float* eW, int K, int off, int q) {
    int n = q / K, k = q - n * K;
    int half_ = n / CDIM, rem = n % CDIM, t = rem / EH, j = rem % EH;
    float v = eW[(size_t)t * (2 * K * EH) + (size_t)(half_ * K + k) * EH + j];
    g_Wstage[off + (((k >> 5) * ABDIM) + n) * 40 + (k & 31)] = __float2half_rn(v);
}
__device__ __forceinline__ void stage_node(const float* nW, int OUTD, int off, int q) {
    int NR = 2 * OUTD;
    int n = q / CDIM, k = q - n * CDIM;
    int t = n / OUTD, j = n - t * OUTD;
    float v = nW[(size_t)t * CDIM * OUTD + (size_t)k * OUTD + j];
    g_Wstage[off + (((k >> 5) * NR) + n) * 40 + (k & 31)] = __float2half_rn(v);
}
__global__ void prep_all(const float* __restrict__ eW0, const float* __restrict__ nW0,
                         const float* __restrict__ eW1, const float* __restrict__ nW1) {
    int idx = blockIdx.x * blockDim.x + threadIdx.x;
    if (idx == 0) { g_n0 = 0; g_c0 = 0; g_c1 = 0; }
    if (idx < 24576)                  stage_edge(eW0, 128, OFF_E0, idx);
    else if (idx < 24576 + 12288)     stage_node(nW0,  64, OFF_N0, idx - 24576);
    else if (idx < 36864 + 12288)     stage_edge(eW1,  64, OFF_E1, idx - 36864);
    else if (idx < 49152 + 24576)     stage_node(nW1, 128, OFF_N1, idx - 49152);
}

// ===========================================================================
// Node-type partition: count type0, then aggregated-atomic assignment.
// ===========================================================================
__global__ void count_kernel(const int* __restrict__ nt, int n) {
    int i = blockIdx.x * 256 + threadIdx.x;
    int is0 = (i < n && nt[i] == 0) ? 1 : 0;
    unsigned m = __ballot_sync(0xffffffffu, is0);
    __shared__ int ws[8];
    if ((threadIdx.x & 31) == 0) ws[threadIdx.x >> 5] = __popc(m);
    __syncthreads();
    if (threadIdx.x == 0) {
        int s = 0;
#pragma unroll
        for (int w = 0; w < 8; w++) s += ws[w];
        atomicAdd(&g_n0, s);
    }
}
__global__ void assign_kernel(const int* __restrict__ nt, int n) {
    int i = blockIdx.x * 256 + threadIdx.x;
    int t = (i < n) ? nt[i] : -1;
    unsigned m0 = __ballot_sync(0xffffffffu, t == 0);
    unsigned m1 = __ballot_sync(0xffffffffu, t == 1);
    int lane = threadIdx.x & 31, warp = threadIdx.x >> 5;
    __shared__ int w0[8], w1[8], b0, b1;
    if (lane == 0) { w0[warp] = __popc(m0); w1[warp] = __popc(m1); }
    __syncthreads();
    if (threadIdx.x == 0) {
        int s0 = 0, s1 = 0, o0[8], o1[8];
#pragma unroll
        for (int w = 0; w < 8; w++) { o0[w] = s0; s0 += w0[w]; o1[w] = s1; s1 += w1[w]; }
#pragma unroll
        for (int w = 0; w < 8; w++) { w0[w] = o0[w]; w1[w] = o1[w]; }
        b0 = atomicAdd(&g_c0, s0);
        b1 = atomicAdd(&g_c1, s1);
    }
    __syncthreads();
    unsigned lt = (1u << lane) - 1u;
    if (t == 0)      g_perm[b0 + w0[warp] + __popc(m0 & lt)] = i;
    else if (t == 1) g_perm[g_n0 + b1 + w1[warp] + __popc(m1 & lt)] = i;
}

// ===========================================================================
// AB GEMM (fp16 mma.sync): g_ABh[row][cb..] = X[row][K] @ W^T. 128 rows/blk,
// 256 thr, CHUNK-wide slab per blockIdx.y. A-fragments direct from global,
// W slab in smem (one barrier). Slab 0 folds edge bias + zeroes accum/cnt.
// TX = float or __half input.
// ===========================================================================
__device__ __forceinline__ uint32_t pack2(float a, float b) {
    __half2 h = __floats2half2_rn(a, b);
    return *reinterpret_cast<uint32_t*>(&h);
}
template <typename TX, int K, int NTOT, int CHUNK, int WOFF, bool ZCNT>
__global__ __launch_bounds__(256) void ab_gemm(const TX* __restrict__ X,
                                               const float* __restrict__ bias, int n) {
    constexpr int NB = CHUNK / 8;
    constexpr int NKC = K / 32;
    __shared__ __align__(16) __half Ws[NKC][CHUNK][40];

    const int tid = threadIdx.x;
    const int lane = tid & 31, wid = tid >> 5;
    const int gid = lane >> 2, tig = lane & 3;
    const int base = blockIdx.x * 128;
    const int cb = blockIdx.y * CHUNK;
    const int wr = wid * 16;

    {
        const __half* wsrc = g_Wstage + WOFF;
        int4* wdst = (int4*)&Ws[0][0][0];
        for (int idx = tid; idx < NKC * CHUNK * 5; idx += 256) {
            int kc = idx / (CHUNK * 5), r = idx - kc * (CHUNK * 5);
            wdst[idx] = ((const int4*)(wsrc + (size_t)(kc * NTOT + cb) * 40))[r];
        }
    }
    __syncthreads();

    const int r0 = base + wr + gid, r1 = r0 + 8;
    const TX* x0 = X + (size_t)min(r0, n - 1) * K;
    const TX* x1 = X + (size_t)min(r1, n - 1) * K;

    float c[NB][4];
#pragma unroll
    for (int nb = 0; nb < NB; nb++)
#pragma unroll
        for (int q = 0; q < 4; q++) c[nb][q] = 0.f;

#pragma unroll
    for (int kc = 0; kc < NKC; kc++) {
#pragma unroll
        for (int ks = 0; ks < 2; ks++) {
            const int kg = kc * 32 + ks * 16 + 2 * tig;
            uint32_t a0, a1, a2, a3;
            if constexpr (sizeof(TX) == 4) {
                float2 f0 = *(const float2*)((const float*)x0 + kg);
                float2 f1 = *(const float2*)((const float*)x1 + kg);
                float2 f2 = *(const float2*)((const float*)x0 + kg + 8);
                float2 f3 = *(const float2*)((const float*)x1 + kg + 8);
                a0 = pack2(f0.x, f0.y); a1 = pack2(f1.x, f1.y);
                a2 = pack2(f2.x, f2.y); a3 = pack2(f3.x, f3.y);
            } else {
                a0 = *(const uint32_t*)((const __half*)x0 + kg);
                a1 = *(const uint32_t*)((const __half*)x1 + kg);
                a2 = *(const uint32_t*)((const __half*)x0 + kg + 8);
                a3 = *(const uint32_t*)((const __half*)x1 + kg + 8);
            }
            const int kk = ks * 16 + 2 * tig;
#pragma unroll
            for (int nb = 0; nb < NB; nb++) {
                uint32_t b0 = *(const uint32_t*)&Ws[kc][nb * 8 + gid][kk];
                uint32_t b1 = *(const uint32_t*)&Ws[kc][nb * 8 + gid][kk + 8];
                asm volatile(
                    "mma.sync.aligned.m16n8k16.row.col.f32.f16.f16.f32 "
                    "{%0,%1,%2,%3}, {%4,%5,%6,%7}, {%8,%9}, {%0,%1,%2,%3};"
                    : "+f"(c[nb][0]), "+f"(c[nb][1]), "+f"(c[nb][2]), "+f"(c[nb][3])
                    : "r"(a0), "r"(a1), "r"(a2), "r"(a3), "r"(b0), "r"(b1));
            }
        }
    }

#pragma unroll
    for (int h = 0; h < 2; h++) {
        int row = base + wr + gid + 8 * h;
        if (row < n) {
#pragma unroll
            for (int nb = 0; nb < NB; nb++) {
                int col = cb + nb * 8 + 2 * tig;
                float vx = c[nb][2 * h], vy = c[nb][2 * h + 1];
                if (blockIdx.y == 0) {              // A half: fold edge bias
                    float2 b = *(const float2*)(bias + col);
                    vx += b.x; vy += b.y;
                }
                *(__half2*)(g_ABh + (size_t)row * ABDIM + col) = __floats2half2_rn(vx, vy);
            }
        }
    }
    // fused zeroing of scatter state (slab 0)
    if (blockIdx.y == 0) {
        float4 z = make_float4(0.f, 0.f, 0.f, 0.f);
        for (int idx = lane; idx < 16 * 24; idx += 32) {
            int r = idx / 24, q = idx - r * 24;
            int row = base + wr + r;
            if (row < n) ((float4*)(g_accum + (size_t)row * CDIM))[q] = z;
        }
        if (ZCNT && lane < 16) {
            int row = base + wr + lane;
            if (row < n) {
                g_cnt[row * NET] = 0.f;
                g_cnt[row * NET + 1] = 0.f;
                g_cnt[row * NET + 2] = 0.f;
            }
        }
    }
}

// ===========================================================================
// Node GEMM over type-partitioned rows: each block handles 128 partitioned
// positions of ONE node type (blockIdx.x vs boundary), computing only that
// type's OUTD columns. X = g_accum/max(cnt,1) (via perm); epilogue bias+relu,
// scattered row writes via perm. HOUT: write fp16 g_Hh, else fp32 out.
// ===========================================================================
template <int NTOT, int OUTD, int WOFF, bool HOUT>
__global__ __launch_bounds__(256) void node_gemm(const float* __restrict__ X,
                                                 const float* __restrict__ cnt,
                                                 const float* __restrict__ bias,
                                                 float* __restrict__ out, int n) {
    constexpr int NB = OUTD / 8;
    constexpr int NKC = 3;                 // K = 96
    __shared__ __align__(16) __half Ws[NKC][OUTD][40];

    const int n0 = g_n0;
    const int nblk0 = (n0 + 127) >> 7;
    const int nblk1 = (n - n0 + 127) >> 7;
    if ((int)blockIdx.x >= nblk0 + nblk1) return;
    const int t = ((int)blockIdx.x < nblk0) ? 0 : 1;
    const int pb = (t == 0) ? (int)blockIdx.x * 128 : n0 + ((int)blockIdx.x - nblk0) * 128;
    const int plim = (t == 0) ? n0 : n;

    const int tid = threadIdx.x;
    const int lane = tid & 31, wid = tid >> 5;
    const int gid = lane >> 2, tig = lane & 3;
    const int wr = wid * 16;
    const int cb = t * OUTD;

    {
        const __half* wsrc = g_Wstage + WOFF;
        int4* wdst = (int4*)&Ws[0][0][0];
        for (int idx = tid; idx < NKC * OUTD * 5; idx += 256) {
            int kc = idx / (OUTD * 5), r = idx - kc * (OUTD * 5);
            wdst[idx] = ((const int4*)(wsrc + (size_t)(kc * NTOT + cb) * 40))[r];
        }
    }
    __syncthreads();

    const int pos0 = pb + wr + gid, pos1 = pos0 + 8;
    const bool v0 = pos0 < plim, v1 = pos1 < plim;
    const int row0 = g_perm[v0 ? pos0 : plim - 1];
    const int row1 = g_perm[v1 ? pos1 : plim - 1];
    const float* x0 = X + (size_t)row0 * CDIM;
    const float* x1 = X + (size_t)row1 * CDIM;

    float c[NB][4];
#pragma unroll
    for (int nb = 0; nb < NB; nb++)
#pragma unroll
        for (int q = 0; q < 4; q++) c[nb][q] = 0.f;

#pragma unroll
    for (int kc = 0; kc < NKC; kc++) {
        float s0 = 1.0f / fmaxf(cnt[row0 * NET + kc], 1.0f);
        float s1 = 1.0f / fmaxf(cnt[row1 * NET + kc], 1.0f);
#pragma unroll
        for (int ks = 0; ks < 2; ks++) {
            const int kg = kc * 32 + ks * 16 + 2 * tig;
            float2 f0 = *(const float2*)(x0 + kg);
            float2 f1 = *(const float2*)(x1 + kg);
            float2 f2 = *(const float2*)(x0 + kg + 8);
            float2 f3 = *(const float2*)(x1 + kg + 8);
            uint32_t a0 = pack2(f0.x * s0, f0.y * s0);
            uint32_t a1 = pack2(f1.x * s1, f1.y * s1);
            uint32_t a2 = pack2(f2.x * s0, f2.y * s0);
            uint32_t a3 = pack2(f3.x * s1, f3.y * s1);
            const int kk = ks * 16 + 2 * tig;
#pragma unroll
            for (int nb = 0; nb < NB; nb++) {
                uint32_t b0 = *(const uint32_t*)&Ws[kc][nb * 8 + gid][kk];
                uint32_t b1 = *(const uint32_t*)&Ws[kc][nb * 8 + gid][kk + 8];
                asm volatile(
                    "mma.sync.aligned.m16n8k16.row.col.f32.f16.f16.f32 "
                    "{%0,%1,%2,%3}, {%4,%5,%6,%7}, {%8,%9}, {%0,%1,%2,%3};"
                    : "+f"(c[nb][0]), "+f"(c[nb][1]), "+f"(c[nb][2]), "+f"(c[nb][3])
                    : "r"(a0), "r"(a1), "r"(a2), "r"(a3), "r"(b0), "r"(b1));
            }
        }
    }

#pragma unroll
    for (int h = 0; h < 2; h++) {
        const bool vh = h ? v1 : v0;
        const int row = h ? row1 : row0;
        if (vh) {
#pragma unroll
            for (int nb = 0; nb < NB; nb++) {
                int col = nb * 8 + 2 * tig;
                float2 b = *(const float2*)(bias + t * OUTD + col);
                float vx = fmaxf(c[nb][2 * h] + b.x, 0.f);
                float vy = fmaxf(c[nb][2 * h + 1] + b.y, 0.f);
                if (HOUT)
                    *(__half2*)(g_Hh + (size_t)row * OUTD + col) = __floats2half2_rn(vx, vy);
                else
                    *(float2*)(out + (size_t)row * OUTD + col) = make_float2(vx, vy);
            }
        }
    }
}

// ===========================================================================
// Edge pass: 8 threads / edge, fp16 gathers, fp32 RED scatter.
// ===========================================================================
template <bool COUNT>
__global__ __launch_bounds__(256) void edge_kernel(const int* __restrict__ ei,
                                                   const int* __restrict__ et, int E) {
    int gid = blockIdx.x * blockDim.x + threadIdx.x;
    int e = gid >> 3;
    if (e >= E) return;
    int l = gid & 7;
    int src = ei[e], dst = ei[E + e], t = et[e];

    uint2 ar = *(const uint2*)(g_ABh + (size_t)src * ABDIM + t * EH + l * 4);
    uint2 br = *(const uint2*)(g_ABh + (size_t)dst * ABDIM + CDIM + t * EH + l * 4);
    float2 a0 = __half22float2(*(__half2*)&ar.x);
    float2 a1 = __half22float2(*(__half2*)&ar.y);
    float2 b0 = __half22float2(*(__half2*)&br.x);
    float2 b1 = __half22float2(*(__half2*)&br.y);
    float mx = fmaxf(a0.x + b0.x, 0.f);
    float my = fmaxf(a0.y + b0.y, 0.f);
    float mz = fmaxf(a1.x + b1.x, 0.f);
    float mw = fmaxf(a1.y + b1.y, 0.f);

    float* p = g_accum + (size_t)dst * CDIM + t * EH + l * 4;
    asm volatile("red.global.add.v4.f32 [%0], {%1,%2,%3,%4};"
                 :: "l"(p), "f"(mx), "f"(my), "f"(mz), "f"(mw) : "memory");
    if (COUNT && l == 0) atomicAdd(g_cnt + (size_t)dst * NET + t, 1.0f);
}

// ===========================================================================
extern "C" void kernel_launch(void* const* d_in, const int* in_sizes, int n_in,
                              void* d_out, int out_size) {
    const float* nf  = (const float*)d_in[0];
    const int*   ei  = (const int*)  d_in[1];
    const int*   et  = (const int*)  d_in[2];
    const int*   nt  = (const int*)  d_in[3];
    const float* eW0 = (const float*)d_in[4];
    const float* eb0 = (const float*)d_in[5];
    const float* nW0 = (const float*)d_in[6];
    const float* nb0 = (const float*)d_in[7];
    const float* eW1 = (const float*)d_in[8];
    const float* eb1 = (const float*)d_in[9];
    const float* nW1 = (const float*)d_in[10];
    const float* nb1 = (const float*)d_in[11];
    float* out = (float*)d_out;

    const int N = in_sizes[3];
    const int E = in_sizes[2];

    float *pAcc, *pCnt;
    __half *pHh;
    cudaGetSymbolAddress((void**)&pAcc, g_accum);
    cudaGetSymbolAddress((void**)&pCnt, g_cnt);
    cudaGetSymbolAddress((void**)&pHh,  g_Hh);

    const int nb128 = (N + 127) / 128;
    const dim3 g2(nb128, 2);
    const int gNode = nb128 + 1;
    const int gEdge = (E * 8 + 255) / 256;
    const int gN = (N + 255) / 256;

    // staging + node-type partition (cheap, once per launch)
    prep_all<<<(73728 + 255) / 256, 256>>>(eW0, nW0, eW1, nW1);
    count_kernel<<<gN, 256>>>(nt, N);
    assign_kernel<<<gN, 256>>>(nt, N);

    // ---------------- layer 0 (128 -> 64) ----------------
    ab_gemm<float, 128, 192, 96, OFF_E0, true><<<g2, 256>>>(nf, eb0, N);
    edge_kernel<true><<<gEdge, 256>>>(ei, et, E);
    node_gemm<128, 64, OFF_N0, true><<<gNode, 256>>>(pAcc, pCnt, nb0, nullptr, N);

    // ---------------- layer 1 (64 -> 128) ----------------
    ab_gemm<__half, 64, 192, 96, OFF_E1, false><<<g2, 256>>>(pHh, eb1, N);
    edge_kernel<false><<<gEdge, 256>>>(ei, et, E);
    node_gemm<256, 128, OFF_N1, false><<<gNode, 256>>>(pAcc, pCnt, nb1, out, N);
}

// round 15
// speedup vs baseline: 1.2608x; 1.0285x over previous
#include <cuda_runtime.h>
#include <cuda_fp16.h>
#include <cstdint>

#define NMAX   50000
#define EH     32
#define NET    3
#define CDIM   96      // NET*EH
#define ABDIM  192     // A(96) | B(96)

// ---- device scratch (static: no allocation allowed) ----
__device__ __half g_ABh[NMAX * ABDIM];   // per-node A|B precompute, fp16 (edge bias folded into A)
__device__ float  g_accum[NMAX * CDIM];  // scatter accumulators (fp32)
__device__ float  g_cnt[NMAX * NET];     // per (node, etype) counts
__device__ __half g_Hh[NMAX * 64];       // layer-0 node output (fp16)
__device__ __half g_Wstage[98304];       // all 4 weight sets staged as [kchunk][n][40] fp16
__device__ int    g_perm[NMAX];          // nodes partitioned by type
__device__ int    g_n0, g_c0, g_c1;      // partition counters

// stage offsets (in halfs)
#define OFF_E0 0
#define OFF_N0 30720
#define OFF_E1 46080
#define OFF_N1 61440

// ===========================================================================
// PTX helpers
// ===========================================================================
__device__ __forceinline__ uint32_t smem_u32(const void* p) {
    uint32_t a;
    asm("{ .reg .u64 t; cvta.to.shared.u64 t, %1; cvt.u32.u64 %0, t; }" : "=r"(a) : "l"(p));
    return a;
}
__device__ __forceinline__ void ldsm4(uint32_t& r0, uint32_t& r1, uint32_t& r2,
                                      uint32_t& r3, uint32_t addr) {
    asm volatile("ldmatrix.sync.aligned.m8n8.x4.shared.b16 {%0,%1,%2,%3}, [%4];"
                 : "=r"(r0), "=r"(r1), "=r"(r2), "=r"(r3) : "r"(addr));
}
#define MMA16816(C, A0, A1, A2, A3, B0, B1) \
    asm volatile("mma.sync.aligned.m16n8k16.row.col.f32.f16.f16.f32 " \
                 "{%0,%1,%2,%3}, {%4,%5,%6,%7}, {%8,%9}, {%0,%1,%2,%3};" \
                 : "+f"((C)[0]), "+f"((C)[1]), "+f"((C)[2]), "+f"((C)[3]) \
                 : "r"(A0), "r"(A1), "r"(A2), "r"(A3), "r"(B0), "r"(B1))

// ===========================================================================
// Combined weight staging (+ zero partition counters)
// ===========================================================================
__device__ __forceinline__ void stage_edge(const float* eW, int K, int off, int q) {
    int n = q / K, k = q - n * K;
    int half_ = n / CDIM, rem = n % CDIM, t = rem / EH, j = rem % EH;
    float v = eW[(size_t)t * (2 * K * EH) + (size_t)(half_ * K + k) * EH + j];
    g_Wstage[off + (((k >> 5) * ABDIM) + n) * 40 + (k & 31)] = __float2half_rn(v);
}
__device__ __forceinline__ void stage_node(const float* nW, int OUTD, int off, int q) {
    int NR = 2 * OUTD;
    int n = q / CDIM, k = q - n * CDIM;
    int t = n / OUTD, j = n - t * OUTD;
    float v = nW[(size_t)t * CDIM * OUTD + (size_t)k * OUTD + j];
    g_Wstage[off + (((k >> 5) * NR) + n) * 40 + (k & 31)] = __float2half_rn(v);
}
__global__ void prep_all(const float* __restrict__ eW0, const float* __restrict__ nW0,
                         const float* __restrict__ eW1, const float* __restrict__ nW1) {
    int idx = blockIdx.x * blockDim.x + threadIdx.x;
    if (idx == 0) { g_n0 = 0; g_c0 = 0; g_c1 = 0; }
    if (idx < 24576)                  stage_edge(eW0, 128, OFF_E0, idx);
    else if (idx < 24576 + 12288)     stage_node(nW0,  64, OFF_N0, idx - 24576);
    else if (idx < 36864 + 12288)     stage_edge(eW1,  64, OFF_E1, idx - 36864);
    else if (idx < 49152 + 24576)     stage_node(nW1, 128, OFF_N1, idx - 49152);
}

// ===========================================================================
// Node-type partition (aggregated atomics)
// ===========================================================================
__global__ void count_kernel(const int* __restrict__ nt, int n) {
    int i = blockIdx.x * 256 + threadIdx.x;
    int is0 = (i < n && nt[i] == 0) ? 1 : 0;
    unsigned m = __ballot_sync(0xffffffffu, is0);
    __shared__ int ws[8];
    if ((threadIdx.x & 31) == 0) ws[threadIdx.x >> 5] = __popc(m);
    __syncthreads();
    if (threadIdx.x == 0) {
        int s = 0;
#pragma unroll
        for (int w = 0; w < 8; w++) s += ws[w];
        atomicAdd(&g_n0, s);
    }
}
__global__ void assign_kernel(const int* __restrict__ nt, int n) {
    int i = blockIdx.x * 256 + threadIdx.x;
    int t = (i < n) ? nt[i] : -1;
    unsigned m0 = __ballot_sync(0xffffffffu, t == 0);
    unsigned m1 = __ballot_sync(0xffffffffu, t == 1);
    int lane = threadIdx.x & 31, warp = threadIdx.x >> 5;
    __shared__ int w0[8], w1[8], b0, b1;
    if (lane == 0) { w0[warp] = __popc(m0); w1[warp] = __popc(m1); }
    __syncthreads();
    if (threadIdx.x == 0) {
        int s0 = 0, s1 = 0, o0[8], o1[8];
#pragma unroll
        for (int w = 0; w < 8; w++) { o0[w] = s0; s0 += w0[w]; o1[w] = s1; s1 += w1[w]; }
#pragma unroll
        for (int w = 0; w < 8; w++) { w0[w] = o0[w]; w1[w] = o1[w]; }
        b0 = atomicAdd(&g_c0, s0);
        b1 = atomicAdd(&g_c1, s1);
    }
    __syncthreads();
    unsigned lt = (1u << lane) - 1u;
    if (t == 0)      g_perm[b0 + w0[warp] + __popc(m0 & lt)] = i;
    else if (t == 1) g_perm[g_n0 + b1 + w1[warp] + __popc(m1 & lt)] = i;
}

// ===========================================================================
// AB GEMM: smem-staged fp16 X + ldmatrix fragments. 128 rows/blk, 256 thr,
// CHUNK-wide slab per blockIdx.y. Slab 0 folds edge bias + zeroes accum/cnt.
// ===========================================================================
template <typename TX, int K, int NTOT, int CHUNK, int WOFF, bool ZCNT>
__global__ __launch_bounds__(256) void ab_gemm(const TX* __restrict__ X,
                                               const float* __restrict__ bias, int n) {
    constexpr int NB = CHUNK / 8;
    constexpr int NKC = K / 32;
    constexpr int XSH = K + 8;                  // halfs per Xs row
    extern __shared__ __align__(16) char sm[];
    __half* Xs = (__half*)sm;                   // [128][XSH]
    __half* Ws = (__half*)(sm + 128 * XSH * 2); // [NKC][CHUNK][40]

    const int tid = threadIdx.x;
    const int lane = tid & 31, wid = tid >> 5;
    const int gid = lane >> 2, tig = lane & 3;
    const int base = blockIdx.x * 128;
    const int cb = blockIdx.y * CHUNK;
    const int wr = wid * 16;

    // ---- W slab: linear int4 copy ----
    {
        const __half* wsrc = g_Wstage + WOFF;
        int4* wdst = (int4*)Ws;
        for (int idx = tid; idx < NKC * CHUNK * 5; idx += 256) {
            int kc = idx / (CHUNK * 5), r = idx - kc * (CHUNK * 5);
            wdst[idx] = ((const int4*)(wsrc + (size_t)(kc * NTOT + cb) * 40))[r];
        }
    }
    // ---- X tile -> smem fp16 (coalesced) ----
    if constexpr (sizeof(TX) == 4) {
        constexpr int K4 = K / 4;
#pragma unroll
        for (int i = 0; i < 128 * K4 / 256; i++) {
            int idx = tid + i * 256;
            int row = idx / K4, k4 = idx - row * K4;
            int grow = min(base + row, n - 1);
            float4 v = *(const float4*)((const float*)X + (size_t)grow * K + k4 * 4);
            uint2 u;
            *(__half2*)&u.x = __floats2half2_rn(v.x, v.y);
            *(__half2*)&u.y = __floats2half2_rn(v.z, v.w);
            *(uint2*)&Xs[row * XSH + k4 * 4] = u;
        }
    } else {
        constexpr int K8 = K / 8;
#pragma unroll
        for (int i = 0; i < 128 * K8 / 256; i++) {
            int idx = tid + i * 256;
            int row = idx / K8, k8 = idx - row * K8;
            int grow = min(base + row, n - 1);
            *(int4*)&Xs[row * XSH + k8 * 8] =
                *(const int4*)((const __half*)X + (size_t)grow * K + k8 * 8);
        }
    }
    __syncthreads();

    // fragment base addresses (bytes)
    const uint32_t aBase = smem_u32(Xs) +
        (((wr + (lane & 15)) * XSH + ((lane >> 4) << 3)) << 1);
    const uint32_t bBase = smem_u32(Ws) +
        (((((lane >> 4) << 3) + (lane & 7)) * 40 + (((lane >> 3) & 1) << 3)) << 1);

    float c[NB][4];
#pragma unroll
    for (int nb = 0; nb < NB; nb++)
#pragma unroll
        for (int q = 0; q < 4; q++) c[nb][q] = 0.f;

#pragma unroll
    for (int kc = 0; kc < NKC; kc++)
#pragma unroll
        for (int ks = 0; ks < 2; ks++) {
            uint32_t a0, a1, a2, a3;
            ldsm4(a0, a1, a2, a3, aBase + ((kc * 32 + ks * 16) << 1));
#pragma unroll
            for (int p = 0; p < NB / 2; p++) {
                uint32_t b0, b1, b2, b3;
                ldsm4(b0, b1, b2, b3,
                      bBase + ((((kc * CHUNK + p * 16) * 40) + ks * 16) << 1));
                MMA16816(c[2 * p],     a0, a1, a2, a3, b0, b1);
                MMA16816(c[2 * p + 1], a0, a1, a2, a3, b2, b3);
            }
        }

#pragma unroll
    for (int h = 0; h < 2; h++) {
        int row = base + wr + gid + 8 * h;
        if (row < n) {
#pragma unroll
            for (int nb = 0; nb < NB; nb++) {
                int col = cb + nb * 8 + 2 * tig;
                float vx = c[nb][2 * h], vy = c[nb][2 * h + 1];
                if (blockIdx.y == 0) {              // A half: fold edge bias
                    float2 b = *(const float2*)(bias + col);
                    vx += b.x; vy += b.y;
                }
                *(__half2*)(g_ABh + (size_t)row * ABDIM + col) = __floats2half2_rn(vx, vy);
            }
        }
    }
    // fused zeroing of scatter state (slab 0)
    if (blockIdx.y == 0) {
        float4 z = make_float4(0.f, 0.f, 0.f, 0.f);
        for (int idx = lane; idx < 16 * 24; idx += 32) {
            int r = idx / 24, q = idx - r * 24;
            int row = base + wr + r;
            if (row < n) ((float4*)(g_accum + (size_t)row * CDIM))[q] = z;
        }
        if (ZCNT && lane < 16) {
            int row = base + wr + lane;
            if (row < n) {
                g_cnt[row * NET] = 0.f;
                g_cnt[row * NET + 1] = 0.f;
                g_cnt[row * NET + 2] = 0.f;
            }
        }
    }
}

// ===========================================================================
// Node GEMM over type-partitioned rows, smem-staged X (mean folded in) +
// ldmatrix fragments. Each block: 128 partitioned positions of one type.
// ===========================================================================
template <int NTOT, int OUTD, int WOFF, bool HOUT>
__global__ __launch_bounds__(256) void node_gemm(const float* __restrict__ X,
                                                 const float* __restrict__ cnt,
                                                 const float* __restrict__ bias,
                                                 float* __restrict__ out, int n) {
    constexpr int NB = OUTD / 8;
    constexpr int NKC = 3;                 // K = 96
    constexpr int XSH = 104;               // 96 + 8 pad
    extern __shared__ __align__(16) char sm[];
    __half* Xs = (__half*)sm;                   // [128][104]
    __half* Ws = (__half*)(sm + 128 * XSH * 2); // [3][OUTD][40]

    const int n0 = g_n0;
    const int nblk0 = (n0 + 127) >> 7;
    const int nblk1 = (n - n0 + 127) >> 7;
    if ((int)blockIdx.x >= nblk0 + nblk1) return;
    const int t = ((int)blockIdx.x < nblk0) ? 0 : 1;
    const int pb = (t == 0) ? (int)blockIdx.x * 128 : n0 + ((int)blockIdx.x - nblk0) * 128;
    const int plim = (t == 0) ? n0 : n;

    const int tid = threadIdx.x;
    const int lane = tid & 31, wid = tid >> 5;
    const int gid = lane >> 2, tig = lane & 3;
    const int wr = wid * 16;
    const int cb = t * OUTD;

    // ---- W slab ----
    {
        const __half* wsrc = g_Wstage + WOFF;
        int4* wdst = (int4*)Ws;
        for (int idx = tid; idx < NKC * OUTD * 5; idx += 256) {
            int kc = idx / (OUTD * 5), r = idx - kc * (OUTD * 5);
            wdst[idx] = ((const int4*)(wsrc + (size_t)(kc * NTOT + cb) * 40))[r];
        }
    }
    // ---- X tile: gather perm rows, scale by 1/cnt, -> fp16 smem ----
#pragma unroll
    for (int i = 0; i < 128 * 24 / 256; i++) {
        int idx = tid + i * 256;
        int row = idx / 24, k4 = idx - row * 24;
        int grow = g_perm[min(pb + row, plim - 1)];
        int kc = k4 >> 3;
        float s = 1.0f / fmaxf(cnt[grow * NET + kc], 1.0f);
        float4 v = *(const float4*)(X + (size_t)grow * CDIM + k4 * 4);
        uint2 u;
        *(__half2*)&u.x = __floats2half2_rn(v.x * s, v.y * s);
        *(__half2*)&u.y = __floats2half2_rn(v.z * s, v.w * s);
        *(uint2*)&Xs[row * XSH + k4 * 4] = u;
    }
    __syncthreads();

    const uint32_t aBase = smem_u32(Xs) +
        (((wr + (lane & 15)) * XSH + ((lane >> 4) << 3)) << 1);
    const uint32_t bBase = smem_u32(Ws) +
        (((((lane >> 4) << 3) + (lane & 7)) * 40 + (((lane >> 3) & 1) << 3)) << 1);

    float c[NB][4];
#pragma unroll
    for (int nb = 0; nb < NB; nb++)
#pragma unroll
        for (int q = 0; q < 4; q++) c[nb][q] = 0.f;

#pragma unroll
    for (int kc = 0; kc < NKC; kc++)
#pragma unroll
        for (int ks = 0; ks < 2; ks++) {
            uint32_t a0, a1, a2, a3;
            ldsm4(a0, a1, a2, a3, aBase + ((kc * 32 + ks * 16) << 1));
#pragma unroll
            for (int p = 0; p < NB / 2; p++) {
                uint32_t b0, b1, b2, b3;
                ldsm4(b0, b1, b2, b3,
                      bBase + ((((kc * OUTD + p * 16) * 40) + ks * 16) << 1));
                MMA16816(c[2 * p],     a0, a1, a2, a3, b0, b1);
                MMA16816(c[2 * p + 1], a0, a1, a2, a3, b2, b3);
            }
        }

#pragma unroll
    for (int h = 0; h < 2; h++) {
        int pos = pb + wr + gid + 8 * h;
        if (pos < plim) {
            int row = g_perm[pos];
#pragma unroll
            for (int nb = 0; nb < NB; nb++) {
                int col = nb * 8 + 2 * tig;
                float2 b = *(const float2*)(bias + t * OUTD + col);
                float vx = fmaxf(c[nb][2 * h] + b.x, 0.f);
                float vy = fmaxf(c[nb][2 * h + 1] + b.y, 0.f);
                if (HOUT)
                    *(__half2*)(g_Hh + (size_t)row * OUTD + col) = __floats2half2_rn(vx, vy);
                else
                    *(float2*)(out + (size_t)row * OUTD + col) = make_float2(vx, vy);
            }
        }
    }
}

// ===========================================================================
// Edge pass: 8 threads / edge, fp16 gathers, fp32 RED scatter.
// ===========================================================================
template <bool COUNT>
__global__ __launch_bounds__(256) void edge_kernel(const int* __restrict__ ei,
                                                   const int* __restrict__ et, int E) {
    int gid = blockIdx.x * blockDim.x + threadIdx.x;
    int e = gid >> 3;
    if (e >= E) return;
    int l = gid & 7;
    int src = ei[e], dst = ei[E + e], t = et[e];

    uint2 ar = *(const uint2*)(g_ABh + (size_t)src * ABDIM + t * EH + l * 4);
    uint2 br = *(const uint2*)(g_ABh + (size_t)dst * ABDIM + CDIM + t * EH + l * 4);
    float2 a0 = __half22float2(*(__half2*)&ar.x);
    float2 a1 = __half22float2(*(__half2*)&ar.y);
    float2 b0 = __half22float2(*(__half2*)&br.x);
    float2 b1 = __half22float2(*(__half2*)&br.y);
    float mx = fmaxf(a0.x + b0.x, 0.f);
    float my = fmaxf(a0.y + b0.y, 0.f);
    float mz = fmaxf(a1.x + b1.x, 0.f);
    float mw = fmaxf(a1.y + b1.y, 0.f);

    float* p = g_accum + (size_t)dst * CDIM + t * EH + l * 4;
    asm volatile("red.global.add.v4.f32 [%0], {%1,%2,%3,%4};"
                 :: "l"(p), "f"(mx), "f"(my), "f"(mz), "f"(mw) : "memory");
    if (COUNT && l == 0) atomicAdd(g_cnt + (size_t)dst * NET + t, 1.0f);
}

// ===========================================================================
extern "C" void kernel_launch(void* const* d_in, const int* in_sizes, int n_in,
                              void* d_out, int out_size) {
    const float* nf  = (const float*)d_in[0];
    const int*   ei  = (const int*)  d_in[1];
    const int*   et  = (const int*)  d_in[2];
    const int*   nt  = (const int*)  d_in[3];
    const float* eW0 = (const float*)d_in[4];
    const float* eb0 = (const float*)d_in[5];
    const float* nW0 = (const float*)d_in[6];
    const float* nb0 = (const float*)d_in[7];
    const float* eW1 = (const float*)d_in[8];
    const float* eb1 = (const float*)d_in[9];
    const float* nW1 = (const float*)d_in[10];
    const float* nb1 = (const float*)d_in[11];
    float* out = (float*)d_out;

    const int N = in_sizes[3];
    const int E = in_sizes[2];

    float *pAcc, *pCnt;
    __half *pHh;
    cudaGetSymbolAddress((void**)&pAcc, g_accum);
    cudaGetSymbolAddress((void**)&pCnt, g_cnt);
    cudaGetSymbolAddress((void**)&pHh,  g_Hh);

    const int nb128 = (N + 127) / 128;
    const dim3 g2(nb128, 2);
    const int gNode = nb128 + 1;
    const int gEdge = (E * 8 + 255) / 256;
    const int gN = (N + 255) / 256;

    // dynamic smem: Xs(128*(K+8)*2) + Ws(NKC*CHUNK*40*2)
    constexpr int S_AB0 = 128 * 136 * 2 + 4 * 96 * 40 * 2;   // 65536
    constexpr int S_AB1 = 128 * 72 * 2 + 2 * 96 * 40 * 2;    // 33792
    constexpr int S_N0  = 128 * 104 * 2 + 3 * 64 * 40 * 2;   // 41984
    constexpr int S_N1  = 128 * 104 * 2 + 3 * 128 * 40 * 2;  // 57344
    cudaFuncSetAttribute(ab_gemm<float, 128, 192, 96, OFF_E0, true>,
                         cudaFuncAttributeMaxDynamicSharedMemorySize, S_AB0);
    cudaFuncSetAttribute(ab_gemm<__half, 64, 192, 96, OFF_E1, false>,
                         cudaFuncAttributeMaxDynamicSharedMemorySize, S_AB1);
    cudaFuncSetAttribute(node_gemm<128, 64, OFF_N0, true>,
                         cudaFuncAttributeMaxDynamicSharedMemorySize, S_N0);
    cudaFuncSetAttribute(node_gemm<256, 128, OFF_N1, false>,
                         cudaFuncAttributeMaxDynamicSharedMemorySize, S_N1);

    // staging + node-type partition
    prep_all<<<(73728 + 255) / 256, 256>>>(eW0, nW0, eW1, nW1);
    count_kernel<<<gN, 256>>>(nt, N);
    assign_kernel<<<gN, 256>>>(nt, N);

    // ---------------- layer 0 (128 -> 64) ----------------
    ab_gemm<float, 128, 192, 96, OFF_E0, true><<<g2, 256, S_AB0>>>(nf, eb0, N);
    edge_kernel<true><<<gEdge, 256>>>(ei, et, E);
    node_gemm<128, 64, OFF_N0, true><<<gNode, 256, S_N0>>>(pAcc, pCnt, nb0, nullptr, N);

    // ---------------- layer 1 (64 -> 128) ----------------
    ab_gemm<__half, 64, 192, 96, OFF_E1, false><<<g2, 256, S_AB1>>>(pHh, eb1, N);
    edge_kernel<false><<<gEdge, 256>>>(ei, et, E);
    node_gemm<256, 128, OFF_N1, false><<<gNode, 256, S_N1>>>(pAcc, pCnt, nb1, out, N);
}